// round 9
// baseline (speedup 1.0000x reference)
#include <cuda_runtime.h>
#include <cuda_bf16.h>
#include <cstdint>
#include <cstddef>

#define NPTS 65536
#define CIN  256
#define COUT 128
#define KOFF 8
#define NTOT 524288.0f   // 8 * NPTS

// ---------------- device scratch (allocation-free rule: __device__ globals) ----
__device__ __align__(256) __nv_bfloat16 g_xh[NPTS * CIN];        // 32 MB
__device__ __align__(256) __nv_bfloat16 g_xl[NPTS * CIN];        // 32 MB
__device__ __align__(256) unsigned char g_wh[KOFF * 4 * 16384];  // 512 KB pre-swizzled SW128 tiles
__device__ __align__(256) unsigned char g_wl[KOFF * 4 * 16384];  // 512 KB
__device__ __align__(16)  float g_psum[4096 * COUT];             // per-CTA channel sums
__device__ __align__(16)  float g_psq [4096 * COUT];
__device__ __align__(16)  float g_scale[COUT];
__device__ __align__(16)  float g_shift[COUT];

// ---------------- helpers ----------------
__device__ __forceinline__ uint32_t smem_u32(const void* p) {
    uint32_t a;
    asm("{ .reg .u64 t; cvta.to.shared.u64 t, %1; cvt.u32.u64 %0, t; }"
        : "=r"(a) : "l"(p));
    return a;
}

#define SW128(o) ((uint32_t)(o) ^ ((((uint32_t)(o)) >> 3) & 0x70u))

#define CPA16(dst, src) \
    asm volatile("cp.async.cg.shared.global [%0], [%1], 16;" :: "r"(dst), "l"(src))
#define CPA_COMMIT() asm volatile("cp.async.commit_group;" ::: "memory")

__device__ __forceinline__ void ldsm4(uint32_t* r, uint32_t a) {
    asm volatile("ldmatrix.sync.aligned.m8n8.x4.shared.b16 {%0,%1,%2,%3}, [%4];"
                 : "=r"(r[0]), "=r"(r[1]), "=r"(r[2]), "=r"(r[3]) : "r"(a));
}

__device__ __forceinline__ void mma16816(float* c, const uint32_t* a,
                                         uint32_t b0, uint32_t b1) {
    asm volatile(
        "mma.sync.aligned.m16n8k16.row.col.f32.bf16.bf16.f32 "
        "{%0,%1,%2,%3}, {%4,%5,%6,%7}, {%8,%9}, {%0,%1,%2,%3};"
        : "+f"(c[0]), "+f"(c[1]), "+f"(c[2]), "+f"(c[3])
        : "r"(a[0]), "r"(a[1]), "r"(a[2]), "r"(a[3]), "r"(b0), "r"(b1));
}

// ---------------- prep kernels ----------------
// Split x (fp32) into bf16 hi + bf16 lo residual.
__global__ void prep_x_kernel(const float* __restrict__ x) {
    const int n4 = NPTS * CIN / 4;
    for (int i = blockIdx.x * blockDim.x + threadIdx.x; i < n4;
         i += gridDim.x * blockDim.x) {
        float4 v = ((const float4*)x)[i];
        __nv_bfloat162 h0 = __floats2bfloat162_rn(v.x, v.y);
        __nv_bfloat162 h1 = __floats2bfloat162_rn(v.z, v.w);
        __nv_bfloat162 l0 = __floats2bfloat162_rn(v.x - __bfloat162float(h0.x),
                                                  v.y - __bfloat162float(h0.y));
        __nv_bfloat162 l1 = __floats2bfloat162_rn(v.z - __bfloat162float(h1.x),
                                                  v.w - __bfloat162float(h1.y));
        ((__nv_bfloat162*)g_xh)[2 * i]     = h0;
        ((__nv_bfloat162*)g_xh)[2 * i + 1] = h1;
        ((__nv_bfloat162*)g_xl)[2 * i]     = l0;
        ((__nv_bfloat162*)g_xl)[2 * i + 1] = l1;
    }
}

// Split + transpose W[k][c][d] -> B tiles (rows = d/cout, K-cols = c/cin),
// pre-swizzled SW128, chunked into 4 tiles of K=64 per offset k.
// Tile = 128 rows x 128 bytes.
__global__ void prep_w_kernel(const float* __restrict__ W) {
    int i = blockIdx.x * blockDim.x + threadIdx.x;
    if (i >= KOFF * CIN * COUT) return;
    int k   = i >> 15;        // / (256*128)
    int rem = i & 32767;
    int c   = rem >> 7;       // cin 0..255
    int d   = rem & 127;      // cout 0..127
    float v = W[i];
    __nv_bfloat16 h = __float2bfloat16(v);
    __nv_bfloat16 l = __float2bfloat16(v - __bfloat162float(h));
    int chunk = c >> 6;
    uint32_t off = SW128((uint32_t)d * 128u + (uint32_t)(c & 63) * 2u);
    size_t base = (size_t)k * 65536u + (size_t)chunk * 16384u + off;
    *(__nv_bfloat16*)(g_wh + base) = h;
    *(__nv_bfloat16*)(g_wl + base) = l;
}

// ---------------- main GEMM + stats kernel (mma.sync path) ----------------
// Dynamic SMEM map:
//   [0      ,  65536)  Bh tiles, chunk c at c*16384 (128 rows x 128B, SW128)
//   [65536  , 131072)  Bl tiles
//   [131072 , 196608)  A double buffer: stage buf at 131072 + buf*32768
//                      (Ah at +0, Al at +16384; each 128 rows x 128B, SW128)
//   Epilogue reuses [0, 67584) as fp32 tile, row stride 132 floats.
#define SM_DYN 196608

__global__ void __launch_bounds__(256, 1)
gemm_bn_kernel(float* __restrict__ out) {
    extern __shared__ char smem[];
    const uint32_t sb = smem_u32(smem);
    const int tid = threadIdx.x;
    const int wid = tid >> 5;
    const int lid = tid & 31;
    const int k = blockIdx.x;
    const int m_base = blockIdx.y << 7;
    const int bid = (blockIdx.y << 3) | k;

    const int m_off = (wid >> 2) << 6;   // 0 or 64
    const int n_off = (wid & 3) << 5;    // 0,32,64,96

    // ---- B load: 128 KB, pre-swizzled, linear copy (group 0) ----
    {
        const char* sh = (const char*)g_wh + (size_t)k * 65536u;
        const char* sl = (const char*)g_wl + (size_t)k * 65536u;
        for (int i = tid; i < 4096; i += 256) {
            CPA16(sb + (uint32_t)(i * 16), sh + (size_t)i * 16);
            CPA16(sb + 65536u + (uint32_t)(i * 16), sl + (size_t)i * 16);
        }
        CPA_COMMIT();
    }

    const char* xh0 = (const char*)g_xh + (size_t)m_base * 512u;  // 512 B/row
    const char* xl0 = (const char*)g_xl + (size_t)m_base * 512u;

    auto load_chunk = [&](int c, int buf) {
        const uint32_t ab = sb + 131072u + (uint32_t)buf * 32768u;
        const size_t coff = (size_t)c * 128u;  // K-chunk: c*64 bf16 = c*128 bytes
        for (int i = tid; i < 1024; i += 256) {
            int r = i >> 3, q = i & 7;
            uint32_t off = SW128((uint32_t)r * 128u + (uint32_t)q * 16u);
            size_t so = (size_t)r * 512u + coff + (size_t)q * 16u;
            CPA16(ab + off, xh0 + so);
            CPA16(ab + 16384u + off, xl0 + so);
        }
        CPA_COMMIT();
    };

    load_chunk(0, 0);   // group 1
    load_chunk(1, 1);   // group 2

    // fp32 accumulators: 4 m-tiles x 4 n-tiles x 4 regs
    float acc[4][4][4];
    #pragma unroll
    for (int mi = 0; mi < 4; ++mi)
        #pragma unroll
        for (int nj = 0; nj < 4; ++nj)
            #pragma unroll
            for (int r = 0; r < 4; ++r) acc[mi][nj][r] = 0.f;

    // per-thread ldmatrix row bookkeeping
    const int ra  = m_off + (lid & 15);       // A row for this lane
    const uint32_t ax7 = (uint32_t)(ra & 7);
    const uint32_t a_roff = (uint32_t)ra * 128u;
    const uint32_t a_half = (uint32_t)(lid >> 4);   // k8 half selector
    const int rb  = n_off + lid;              // B row (n) for this lane
    const uint32_t bx7 = (uint32_t)(rb & 7);
    const uint32_t b_roff = (uint32_t)rb * 128u;

    for (int c = 0; c < 4; ++c) {
        const int buf = c & 1;
        if (c < 3) asm volatile("cp.async.wait_group 1;" ::: "memory");
        else       asm volatile("cp.async.wait_group 0;" ::: "memory");
        __syncthreads();

        const uint32_t a_hi_b = sb + 131072u + (uint32_t)buf * 32768u;
        const uint32_t a_lo_b = a_hi_b + 16384u;
        const uint32_t b_hi_b = sb + (uint32_t)c * 16384u;
        const uint32_t b_lo_b = b_hi_b + 65536u;

        #pragma unroll
        for (int ks = 0; ks < 4; ++ks) {
            uint32_t a_hi[4][4], a_lo[4][4];
            uint32_t b_hi0[4], b_hi1[4], b_lo0[4], b_lo1[4];

            const uint32_t sA = (uint32_t)(ks * 2) + a_half;
            #pragma unroll
            for (int mi = 0; mi < 4; ++mi) {
                uint32_t aoff = a_roff + (uint32_t)(mi * 2048) + ((sA ^ ax7) << 4);
                ldsm4(a_hi[mi], a_hi_b + aoff);
                ldsm4(a_lo[mi], a_lo_b + aoff);
            }
            const uint32_t s0 = (uint32_t)(ks * 2), s1 = s0 + 1u;
            const uint32_t bo0 = b_roff + ((s0 ^ bx7) << 4);
            const uint32_t bo1 = b_roff + ((s1 ^ bx7) << 4);
            ldsm4(b_hi0, b_hi_b + bo0);
            ldsm4(b_hi1, b_hi_b + bo1);
            ldsm4(b_lo0, b_lo_b + bo0);
            ldsm4(b_lo1, b_lo_b + bo1);

            #pragma unroll
            for (int mi = 0; mi < 4; ++mi)
                #pragma unroll
                for (int nj = 0; nj < 4; ++nj) {
                    mma16816(acc[mi][nj], a_hi[mi], b_hi0[nj], b_hi1[nj]);
                    mma16816(acc[mi][nj], a_hi[mi], b_lo0[nj], b_lo1[nj]);
                    mma16816(acc[mi][nj], a_lo[mi], b_hi0[nj], b_hi1[nj]);
                }
        }
        __syncthreads();
        if (c < 2) load_chunk(c + 2, buf);   // groups 3, 4
    }

    // ---- epilogue: fragments -> padded smem, stats partials, coalesced stores ----
    float* ep = (float*)smem;  // 128 rows x 132 floats (B region dead now)
    {
        const int er = m_off + (lid >> 2);
        const int ec = n_off + (lid & 3) * 2;
        #pragma unroll
        for (int mi = 0; mi < 4; ++mi) {
            #pragma unroll
            for (int nj = 0; nj < 4; ++nj) {
                int r0 = er + mi * 16;
                int cc = ec + nj * 8;
                *(float2*)&ep[r0 * 132 + cc]       = *(float2*)&acc[mi][nj][0];
                *(float2*)&ep[(r0 + 8) * 132 + cc] = *(float2*)&acc[mi][nj][2];
            }
        }
    }
    __syncthreads();

    // per-CTA channel partial sum / sumsq (deterministic, conflict-free LDS)
    if (tid < 128) {
        float s = 0.f, q = 0.f;
        #pragma unroll 4
        for (int r2 = 0; r2 < 128; ++r2) {
            float v = ep[r2 * 132 + tid];
            s += v;
            q = fmaf(v, v, q);
        }
        g_psum[(size_t)bid * 128 + tid] = s;
        g_psq [(size_t)bid * 128 + tid] = q;
    }

    // coalesced stores of the raw tile
    {
        float4* out4 = (float4*)out;
        const size_t rbase = (size_t)k * NPTS + (size_t)m_base;
        for (int i = tid; i < 4096; i += 256) {
            int row = i >> 5, c4 = i & 31;
            float4 v = *(float4*)&ep[row * 132 + c4 * 4];
            out4[(rbase + (size_t)row) * 32 + c4] = v;
        }
    }
}

// ---------------- stats reduce: 4096 partials -> scale/shift ----------------
__global__ void reduce_kernel(const float* __restrict__ gamma,
                              const float* __restrict__ beta) {
    __shared__ float ss[256];
    __shared__ float sq[256];
    const int ch = blockIdx.x;
    const int tid = threadIdx.x;
    float s = 0.f, q = 0.f;
    for (int j = tid; j < 4096; j += 256) {
        s += g_psum[(size_t)j * 128 + ch];
        q += g_psq [(size_t)j * 128 + ch];
    }
    ss[tid] = s; sq[tid] = q;
    __syncthreads();
    for (int off = 128; off > 0; off >>= 1) {
        if (tid < off) { ss[tid] += ss[tid + off]; sq[tid] += sq[tid + off]; }
        __syncthreads();
    }
    if (tid == 0) {
        float mean = ss[0] / NTOT;
        float var  = sq[0] / NTOT - mean * mean;
        float sc   = gamma[ch] * rsqrtf(var + 1e-5f);
        g_scale[ch] = sc;
        g_shift[ch] = beta[ch] - mean * sc;
    }
}

// ---------------- fused affine + ReLU, in place, float4 ----------------
__global__ void norm_kernel(float* __restrict__ out) {
    const size_t n4 = (size_t)NPTS * KOFF * 32;  // rows * (128/4)
    float4* o = (float4*)out;
    for (size_t i = (size_t)blockIdx.x * blockDim.x + threadIdx.x; i < n4;
         i += (size_t)gridDim.x * blockDim.x) {
        int g = (int)(i & 31);
        float4 sc = ((const float4*)g_scale)[g];
        float4 sh = ((const float4*)g_shift)[g];
        float4 v = o[i];
        v.x = fmaxf(fmaf(v.x, sc.x, sh.x), 0.f);
        v.y = fmaxf(fmaf(v.y, sc.y, sh.y), 0.f);
        v.z = fmaxf(fmaf(v.z, sc.z, sh.z), 0.f);
        v.w = fmaxf(fmaf(v.w, sc.w, sh.w), 0.f);
        o[i] = v;
    }
}

// ---------------- launch ----------------
extern "C" void kernel_launch(void* const* d_in, const int* in_sizes, int n_in,
                              void* d_out, int out_size) {
    const float* x     = (const float*)d_in[0];
    const float* W     = (const float*)d_in[1];
    const float* gamma = (const float*)d_in[2];
    const float* beta  = (const float*)d_in[3];
    float* out = (float*)d_out;

    cudaFuncSetAttribute(gemm_bn_kernel,
                         cudaFuncAttributeMaxDynamicSharedMemorySize, SM_DYN);

    prep_x_kernel<<<2048, 256>>>(x);
    prep_w_kernel<<<1024, 256>>>(W);
    gemm_bn_kernel<<<dim3(8, 512), 256, SM_DYN>>>(out);
    reduce_kernel<<<128, 256>>>(gamma, beta);
    norm_kernel<<<16384, 256>>>(out);
}

// round 11
// speedup vs baseline: 1.2243x; 1.2243x over previous
#include <cuda_runtime.h>
#include <cuda_fp16.h>
#include <cstdint>
#include <cstddef>

#define NPTS 65536
#define CIN  256
#define COUT 128
#define KOFF 8
#define NTOT 524288.0f   // 8 * NPTS

// ---------------- device scratch (allocation-free rule: __device__ globals) ----
__device__ __align__(256) __half g_xh[NPTS * CIN];               // 32 MB (fp16 x)
__device__ __align__(256) unsigned char g_wh[KOFF * 4 * 16384];  // 512 KB pre-swizzled SW128 tiles
__device__ __align__(256) unsigned char g_wl[KOFF * 4 * 16384];  // 512 KB (fp16 W residual)
__device__ __align__(16)  float g_psum[4096 * COUT];             // per-CTA channel sums
__device__ __align__(16)  float g_psq [4096 * COUT];
__device__ __align__(16)  float g_scale[COUT];
__device__ __align__(16)  float g_shift[COUT];

// ---------------- helpers ----------------
__device__ __forceinline__ uint32_t smem_u32(const void* p) {
    uint32_t a;
    asm("{ .reg .u64 t; cvta.to.shared.u64 t, %1; cvt.u32.u64 %0, t; }"
        : "=r"(a) : "l"(p));
    return a;
}

#define SW128(o) ((uint32_t)(o) ^ ((((uint32_t)(o)) >> 3) & 0x70u))

#define CPA16(dst, src) \
    asm volatile("cp.async.cg.shared.global [%0], [%1], 16;" :: "r"(dst), "l"(src))
#define CPA_COMMIT() asm volatile("cp.async.commit_group;" ::: "memory")

__device__ __forceinline__ void ldsm4(uint32_t* r, uint32_t a) {
    asm volatile("ldmatrix.sync.aligned.m8n8.x4.shared.b16 {%0,%1,%2,%3}, [%4];"
                 : "=r"(r[0]), "=r"(r[1]), "=r"(r[2]), "=r"(r[3]) : "r"(a));
}

__device__ __forceinline__ void mma16816(float* c, const uint32_t* a,
                                         uint32_t b0, uint32_t b1) {
    asm volatile(
        "mma.sync.aligned.m16n8k16.row.col.f32.f16.f16.f32 "
        "{%0,%1,%2,%3}, {%4,%5,%6,%7}, {%8,%9}, {%0,%1,%2,%3};"
        : "+f"(c[0]), "+f"(c[1]), "+f"(c[2]), "+f"(c[3])
        : "r"(a[0]), "r"(a[1]), "r"(a[2]), "r"(a[3]), "r"(b0), "r"(b1));
}

// ---------------- prep kernels ----------------
// x (fp32) -> fp16 (single term; residual dropped, rel err ~2.8e-4 < 1e-3).
__global__ void prep_x_kernel(const float* __restrict__ x) {
    const int n4 = NPTS * CIN / 4;
    for (int i = blockIdx.x * blockDim.x + threadIdx.x; i < n4;
         i += gridDim.x * blockDim.x) {
        float4 v = ((const float4*)x)[i];
        __half2 h0 = __floats2half2_rn(v.x, v.y);
        __half2 h1 = __floats2half2_rn(v.z, v.w);
        ((__half2*)g_xh)[2 * i]     = h0;
        ((__half2*)g_xh)[2 * i + 1] = h1;
    }
}

// Split + transpose W[k][c][d] -> B tiles (rows = d/cout, K-cols = c/cin),
// fp16 hi + fp16 residual, pre-swizzled SW128, 4 tiles of K=64 per offset k.
// Tile = 128 rows x 128 bytes.
__global__ void prep_w_kernel(const float* __restrict__ W) {
    int i = blockIdx.x * blockDim.x + threadIdx.x;
    if (i >= KOFF * CIN * COUT) return;
    int k   = i >> 15;        // / (256*128)
    int rem = i & 32767;
    int c   = rem >> 7;       // cin 0..255
    int d   = rem & 127;      // cout 0..127
    float v = W[i];
    __half h = __float2half_rn(v);
    __half l = __float2half_rn(v - __half2float(h));
    int chunk = c >> 6;
    uint32_t off = SW128((uint32_t)d * 128u + (uint32_t)(c & 63) * 2u);
    size_t base = (size_t)k * 65536u + (size_t)chunk * 16384u + off;
    *(__half*)(g_wh + base) = h;
    *(__half*)(g_wl + base) = l;
}

// ---------------- main GEMM + stats kernel (mma.sync fp16, 2-term) ----------
// Dynamic SMEM map:
//   [0      ,  65536)  Bh tiles, chunk c at c*16384 (128 rows x 128B, SW128)
//   [65536  , 131072)  Bl tiles
//   [131072 , 163840)  A double buffer: stage buf at 131072 + buf*16384
//                      (128 rows x 128B, SW128)
//   Epilogue reuses [0, 67584) as fp32 tile, row stride 132 floats.
#define SM_DYN 163840

__global__ void __launch_bounds__(256, 1)
gemm_bn_kernel(float* __restrict__ out) {
    extern __shared__ char smem[];
    const uint32_t sb = smem_u32(smem);
    const int tid = threadIdx.x;
    const int wid = tid >> 5;
    const int lid = tid & 31;
    const int k = blockIdx.x;
    const int m_base = blockIdx.y << 7;
    const int bid = (blockIdx.y << 3) | k;

    const int m_off = (wid >> 2) << 6;   // 0 or 64
    const int n_off = (wid & 3) << 5;    // 0,32,64,96

    // ---- B load: 128 KB, pre-swizzled, linear copy (group 0) ----
    {
        const char* sh = (const char*)g_wh + (size_t)k * 65536u;
        const char* sl = (const char*)g_wl + (size_t)k * 65536u;
        for (int i = tid; i < 4096; i += 256) {
            CPA16(sb + (uint32_t)(i * 16), sh + (size_t)i * 16);
            CPA16(sb + 65536u + (uint32_t)(i * 16), sl + (size_t)i * 16);
        }
        CPA_COMMIT();
    }

    const char* xh0 = (const char*)g_xh + (size_t)m_base * 512u;  // 512 B/row

    auto load_chunk = [&](int c, int buf) {
        const uint32_t ab = sb + 131072u + (uint32_t)buf * 16384u;
        const size_t coff = (size_t)c * 128u;  // K-chunk: c*64 fp16 = c*128 bytes
        for (int i = tid; i < 1024; i += 256) {
            int r = i >> 3, q = i & 7;
            uint32_t off = SW128((uint32_t)r * 128u + (uint32_t)q * 16u);
            CPA16(ab + off, xh0 + (size_t)r * 512u + coff + (size_t)q * 16u);
        }
        CPA_COMMIT();
    };

    load_chunk(0, 0);   // group 1
    load_chunk(1, 1);   // group 2

    // fp32 accumulators: 4 m-tiles x 4 n-tiles x 4 regs
    float acc[4][4][4];
    #pragma unroll
    for (int mi = 0; mi < 4; ++mi)
        #pragma unroll
        for (int nj = 0; nj < 4; ++nj)
            #pragma unroll
            for (int r = 0; r < 4; ++r) acc[mi][nj][r] = 0.f;

    // per-thread ldmatrix row bookkeeping
    const int ra  = m_off + (lid & 15);       // A row for this lane
    const uint32_t ax7 = (uint32_t)(ra & 7);
    const uint32_t a_roff = (uint32_t)ra * 128u;
    const uint32_t a_half = (uint32_t)(lid >> 4);   // k8 half selector
    const int rb  = n_off + lid;              // B row (n) for this lane
    const uint32_t bx7 = (uint32_t)(rb & 7);
    const uint32_t b_roff = (uint32_t)rb * 128u;

    for (int c = 0; c < 4; ++c) {
        const int buf = c & 1;
        if (c < 3) asm volatile("cp.async.wait_group 1;" ::: "memory");
        else       asm volatile("cp.async.wait_group 0;" ::: "memory");
        __syncthreads();

        const uint32_t a_b    = sb + 131072u + (uint32_t)buf * 16384u;
        const uint32_t b_hi_b = sb + (uint32_t)c * 16384u;
        const uint32_t b_lo_b = b_hi_b + 65536u;

        #pragma unroll
        for (int ks = 0; ks < 4; ++ks) {
            uint32_t a[4][4];
            uint32_t b_hi0[4], b_hi1[4], b_lo0[4], b_lo1[4];

            const uint32_t sA = (uint32_t)(ks * 2) + a_half;
            #pragma unroll
            for (int mi = 0; mi < 4; ++mi) {
                uint32_t aoff = a_roff + (uint32_t)(mi * 2048) + ((sA ^ ax7) << 4);
                ldsm4(a[mi], a_b + aoff);
            }
            const uint32_t s0 = (uint32_t)(ks * 2), s1 = s0 + 1u;
            const uint32_t bo0 = b_roff + ((s0 ^ bx7) << 4);
            const uint32_t bo1 = b_roff + ((s1 ^ bx7) << 4);
            ldsm4(b_hi0, b_hi_b + bo0);
            ldsm4(b_hi1, b_hi_b + bo1);
            ldsm4(b_lo0, b_lo_b + bo0);
            ldsm4(b_lo1, b_lo_b + bo1);

            #pragma unroll
            for (int mi = 0; mi < 4; ++mi)
                #pragma unroll
                for (int nj = 0; nj < 4; ++nj) {
                    mma16816(acc[mi][nj], a[mi], b_hi0[nj], b_hi1[nj]);
                    mma16816(acc[mi][nj], a[mi], b_lo0[nj], b_lo1[nj]);
                }
        }
        __syncthreads();
        if (c < 2) load_chunk(c + 2, buf);   // groups 3, 4
    }

    // ---- epilogue: fragments -> padded smem, stats partials, coalesced stores ----
    float* ep = (float*)smem;  // 128 rows x 132 floats (B region dead now)
    {
        const int er = m_off + (lid >> 2);
        const int ec = n_off + (lid & 3) * 2;
        #pragma unroll
        for (int mi = 0; mi < 4; ++mi) {
            #pragma unroll
            for (int nj = 0; nj < 4; ++nj) {
                int r0 = er + mi * 16;
                int cc = ec + nj * 8;
                *(float2*)&ep[r0 * 132 + cc]       = *(float2*)&acc[mi][nj][0];
                *(float2*)&ep[(r0 + 8) * 132 + cc] = *(float2*)&acc[mi][nj][2];
            }
        }
    }
    __syncthreads();

    // per-CTA channel partial sum / sumsq (deterministic, conflict-free LDS)
    if (tid < 128) {
        float s = 0.f, q = 0.f;
        #pragma unroll 4
        for (int r2 = 0; r2 < 128; ++r2) {
            float v = ep[r2 * 132 + tid];
            s += v;
            q = fmaf(v, v, q);
        }
        g_psum[(size_t)bid * 128 + tid] = s;
        g_psq [(size_t)bid * 128 + tid] = q;
    }

    // coalesced stores of the raw tile
    {
        float4* out4 = (float4*)out;
        const size_t rbase = (size_t)k * NPTS + (size_t)m_base;
        for (int i = tid; i < 4096; i += 256) {
            int row = i >> 5, c4 = i & 31;
            float4 v = *(float4*)&ep[row * 132 + c4 * 4];
            out4[(rbase + (size_t)row) * 32 + c4] = v;
        }
    }
}

// ---------------- stats reduce: 4096 partials -> scale/shift ----------------
__global__ void reduce_kernel(const float* __restrict__ gamma,
                              const float* __restrict__ beta) {
    __shared__ float ss[256];
    __shared__ float sq[256];
    const int ch = blockIdx.x;
    const int tid = threadIdx.x;
    float s = 0.f, q = 0.f;
    for (int j = tid; j < 4096; j += 256) {
        s += g_psum[(size_t)j * 128 + ch];
        q += g_psq [(size_t)j * 128 + ch];
    }
    ss[tid] = s; sq[tid] = q;
    __syncthreads();
    for (int off = 128; off > 0; off >>= 1) {
        if (tid < off) { ss[tid] += ss[tid + off]; sq[tid] += sq[tid + off]; }
        __syncthreads();
    }
    if (tid == 0) {
        float mean = ss[0] / NTOT;
        float var  = sq[0] / NTOT - mean * mean;
        float sc   = gamma[ch] * rsqrtf(var + 1e-5f);
        g_scale[ch] = sc;
        g_shift[ch] = beta[ch] - mean * sc;
    }
}

// ---------------- fused affine + ReLU, in place, float4 ----------------
__global__ void norm_kernel(float* __restrict__ out) {
    const size_t n4 = (size_t)NPTS * KOFF * 32;  // rows * (128/4)
    float4* o = (float4*)out;
    for (size_t i = (size_t)blockIdx.x * blockDim.x + threadIdx.x; i < n4;
         i += (size_t)gridDim.x * blockDim.x) {
        int g = (int)(i & 31);
        float4 sc = ((const float4*)g_scale)[g];
        float4 sh = ((const float4*)g_shift)[g];
        float4 v = o[i];
        v.x = fmaxf(fmaf(v.x, sc.x, sh.x), 0.f);
        v.y = fmaxf(fmaf(v.y, sc.y, sh.y), 0.f);
        v.z = fmaxf(fmaf(v.z, sc.z, sh.z), 0.f);
        v.w = fmaxf(fmaf(v.w, sc.w, sh.w), 0.f);
        o[i] = v;
    }
}

// ---------------- launch ----------------
extern "C" void kernel_launch(void* const* d_in, const int* in_sizes, int n_in,
                              void* d_out, int out_size) {
    const float* x     = (const float*)d_in[0];
    const float* W     = (const float*)d_in[1];
    const float* gamma = (const float*)d_in[2];
    const float* beta  = (const float*)d_in[3];
    float* out = (float*)d_out;

    cudaFuncSetAttribute(gemm_bn_kernel,
                         cudaFuncAttributeMaxDynamicSharedMemorySize, SM_DYN);

    prep_x_kernel<<<2048, 256>>>(x);
    prep_w_kernel<<<1024, 256>>>(W);
    gemm_bn_kernel<<<dim3(8, 512), 256, SM_DYN>>>(out);
    reduce_kernel<<<128, 256>>>(gamma, beta);
    norm_kernel<<<16384, 256>>>(out);
}

// round 14
// speedup vs baseline: 1.2646x; 1.0329x over previous
#include <cuda_runtime.h>
#include <cuda_fp16.h>
#include <cstdint>
#include <cstddef>

#define NPTS 65536
#define CIN  256
#define COUT 128
#define KOFF 8
#define NTOT 524288.0f   // 8 * NPTS

// ---------------- device scratch (allocation-free rule: __device__ globals) ----
__device__ __align__(256) __half g_xh[NPTS * CIN];               // 32 MB (fp16 x)
__device__ __align__(256) unsigned char g_wh[KOFF * 4 * 16384];  // 512 KB pre-swizzled SW128 tiles
__device__ __align__(256) unsigned char g_wl[KOFF * 4 * 16384];  // 512 KB (fp16 W residual)
__device__ __align__(16)  float g_psum[2048 * COUT];             // per-CTA channel sums
__device__ __align__(16)  float g_psq [2048 * COUT];
__device__ __align__(16)  float g_scale[COUT];
__device__ __align__(16)  float g_shift[COUT];

// ---------------- helpers ----------------
__device__ __forceinline__ uint32_t smem_u32(const void* p) {
    uint32_t a;
    asm("{ .reg .u64 t; cvta.to.shared.u64 t, %1; cvt.u32.u64 %0, t; }"
        : "=r"(a) : "l"(p));
    return a;
}

#define SW128(o) ((uint32_t)(o) ^ ((((uint32_t)(o)) >> 3) & 0x70u))

#define CPA16(dst, src) \
    asm volatile("cp.async.cg.shared.global [%0], [%1], 16;" :: "r"(dst), "l"(src))
#define CPA_COMMIT() asm volatile("cp.async.commit_group;" ::: "memory")

__device__ __forceinline__ void ldsm4(uint32_t* r, uint32_t a) {
    asm volatile("ldmatrix.sync.aligned.m8n8.x4.shared.b16 {%0,%1,%2,%3}, [%4];"
                 : "=r"(r[0]), "=r"(r[1]), "=r"(r[2]), "=r"(r[3]) : "r"(a));
}

__device__ __forceinline__ void mma16816(float* c, const uint32_t* a,
                                         uint32_t b0, uint32_t b1) {
    asm volatile(
        "mma.sync.aligned.m16n8k16.row.col.f32.f16.f16.f32 "
        "{%0,%1,%2,%3}, {%4,%5,%6,%7}, {%8,%9}, {%0,%1,%2,%3};"
        : "+f"(c[0]), "+f"(c[1]), "+f"(c[2]), "+f"(c[3])
        : "r"(a[0]), "r"(a[1]), "r"(a[2]), "r"(a[3]), "r"(b0), "r"(b1));
}

// ---------------- prep kernels ----------------
// x (fp32) -> fp16 (single term; residual dropped, rel err ~2.8e-4 < 1e-3).
__global__ void prep_x_kernel(const float* __restrict__ x) {
    const int n4 = NPTS * CIN / 4;
    for (int i = blockIdx.x * blockDim.x + threadIdx.x; i < n4;
         i += gridDim.x * blockDim.x) {
        float4 v = ((const float4*)x)[i];
        __half2 h0 = __floats2half2_rn(v.x, v.y);
        __half2 h1 = __floats2half2_rn(v.z, v.w);
        ((__half2*)g_xh)[2 * i]     = h0;
        ((__half2*)g_xh)[2 * i + 1] = h1;
    }
}

// Split + transpose W[k][c][d] -> B tiles (rows = d/cout, K-cols = c/cin),
// fp16 hi + fp16 residual, pre-swizzled SW128, 4 tiles of K=64 per offset k.
// Tile = 128 rows x 128 bytes.
__global__ void prep_w_kernel(const float* __restrict__ W) {
    int i = blockIdx.x * blockDim.x + threadIdx.x;
    if (i >= KOFF * CIN * COUT) return;
    int k   = i >> 15;        // / (256*128)
    int rem = i & 32767;
    int c   = rem >> 7;       // cin 0..255
    int d   = rem & 127;      // cout 0..127
    float v = W[i];
    __half h = __float2half_rn(v);
    __half l = __float2half_rn(v - __half2float(h));
    int chunk = c >> 6;
    uint32_t off = SW128((uint32_t)d * 128u + (uint32_t)(c & 63) * 2u);
    size_t base = (size_t)k * 65536u + (size_t)chunk * 16384u + off;
    *(__half*)(g_wh + base) = h;
    *(__half*)(g_wl + base) = l;
}

// ---------------- main GEMM + stats kernel (256x128 tile, 512 threads) ------
// Dynamic SMEM map:
//   [0      ,  65536)  Bh tiles, chunk c at c*16384 (128 rows x 128B, SW128)
//   [65536  , 131072)  Bl tiles
//   [131072 , 196608)  A double buffer: stage buf at 131072 + buf*32768
//                      (256 rows x 128B, SW128)
//   Epilogue reuses [0, 135168) as fp32 tile, 256 rows x 132 floats.
#define SM_DYN 196608

__global__ void __launch_bounds__(512, 1)
gemm_bn_kernel(float* __restrict__ out) {
    extern __shared__ char smem[];
    const uint32_t sb = smem_u32(smem);
    const int tid = threadIdx.x;
    const int wid = tid >> 5;
    const int lid = tid & 31;
    const int k = blockIdx.x;
    const int m_base = blockIdx.y << 8;          // 256-row tiles
    const int bid = (blockIdx.y << 3) | k;       // 0..2047

    const int m_off = (wid >> 2) << 6;   // 0,64,128,192
    const int n_off = (wid & 3) << 5;    // 0,32,64,96

    // ---- B load: 128 KB, pre-swizzled, linear copy (group 0) ----
    {
        const char* sh = (const char*)g_wh + (size_t)k * 65536u;
        const char* sl = (const char*)g_wl + (size_t)k * 65536u;
        for (int i = tid; i < 4096; i += 512) {
            CPA16(sb + (uint32_t)(i * 16), sh + (size_t)i * 16);
            CPA16(sb + 65536u + (uint32_t)(i * 16), sl + (size_t)i * 16);
        }
        CPA_COMMIT();
    }

    const char* xh0 = (const char*)g_xh + (size_t)m_base * 512u;  // 512 B/row

    auto load_chunk = [&](int c, int buf) {
        const uint32_t ab = sb + 131072u + (uint32_t)buf * 32768u;
        const size_t coff = (size_t)c * 128u;  // K-chunk: c*64 fp16 = c*128 bytes
        for (int i = tid; i < 2048; i += 512) {
            int r = i >> 3, q = i & 7;           // r: 0..255 rows
            uint32_t off = SW128((uint32_t)r * 128u + (uint32_t)q * 16u);
            CPA16(ab + off, xh0 + (size_t)r * 512u + coff + (size_t)q * 16u);
        }
        CPA_COMMIT();
    };

    load_chunk(0, 0);   // group 1
    load_chunk(1, 1);   // group 2

    // fp32 accumulators: 4 m-tiles x 4 n-tiles x 4 regs (warp tile 64x32)
    float acc[4][4][4];
    #pragma unroll
    for (int mi = 0; mi < 4; ++mi)
        #pragma unroll
        for (int nj = 0; nj < 4; ++nj)
            #pragma unroll
            for (int r = 0; r < 4; ++r) acc[mi][nj][r] = 0.f;

    // per-thread ldmatrix row bookkeeping
    const int ra  = m_off + (lid & 15);       // A row for this lane
    const uint32_t ax7 = (uint32_t)(ra & 7);
    const uint32_t a_roff = (uint32_t)ra * 128u;
    const uint32_t a_half = (uint32_t)(lid >> 4);   // k8 half selector
    const int rb  = n_off + lid;              // B row (n) for this lane
    const uint32_t bx7 = (uint32_t)(rb & 7);
    const uint32_t b_roff = (uint32_t)rb * 128u;

    for (int c = 0; c < 4; ++c) {
        const int buf = c & 1;
        if (c < 3) asm volatile("cp.async.wait_group 1;" ::: "memory");
        else       asm volatile("cp.async.wait_group 0;" ::: "memory");
        __syncthreads();

        const uint32_t a_b    = sb + 131072u + (uint32_t)buf * 32768u;
        const uint32_t b_hi_b = sb + (uint32_t)c * 16384u;
        const uint32_t b_lo_b = b_hi_b + 65536u;

        #pragma unroll
        for (int ks = 0; ks < 4; ++ks) {
            uint32_t a[4][4];
            uint32_t b_hi0[4], b_hi1[4], b_lo0[4], b_lo1[4];

            const uint32_t sA = (uint32_t)(ks * 2) + a_half;
            #pragma unroll
            for (int mi = 0; mi < 4; ++mi) {
                uint32_t aoff = a_roff + (uint32_t)(mi * 2048) + ((sA ^ ax7) << 4);
                ldsm4(a[mi], a_b + aoff);
            }
            const uint32_t s0 = (uint32_t)(ks * 2), s1 = s0 + 1u;
            const uint32_t bo0 = b_roff + ((s0 ^ bx7) << 4);
            const uint32_t bo1 = b_roff + ((s1 ^ bx7) << 4);
            ldsm4(b_hi0, b_hi_b + bo0);
            ldsm4(b_hi1, b_hi_b + bo1);
            ldsm4(b_lo0, b_lo_b + bo0);
            ldsm4(b_lo1, b_lo_b + bo1);

            #pragma unroll
            for (int mi = 0; mi < 4; ++mi)
                #pragma unroll
                for (int nj = 0; nj < 4; ++nj) {
                    mma16816(acc[mi][nj], a[mi], b_hi0[nj], b_hi1[nj]);
                    mma16816(acc[mi][nj], a[mi], b_lo0[nj], b_lo1[nj]);
                }
        }
        __syncthreads();
        if (c < 2) load_chunk(c + 2, buf);   // groups 3, 4
    }

    // ---- epilogue: fragments -> padded smem, stats partials, coalesced stores ----
    float* ep = (float*)smem;  // 256 rows x 132 floats (B region dead now)
    {
        const int er = m_off + (lid >> 2);
        const int ec = n_off + (lid & 3) * 2;
        #pragma unroll
        for (int mi = 0; mi < 4; ++mi) {
            #pragma unroll
            for (int nj = 0; nj < 4; ++nj) {
                int r0 = er + mi * 16;
                int cc = ec + nj * 8;
                *(float2*)&ep[r0 * 132 + cc]       = *(float2*)&acc[mi][nj][0];
                *(float2*)&ep[(r0 + 8) * 132 + cc] = *(float2*)&acc[mi][nj][2];
            }
        }
    }
    __syncthreads();

    // per-CTA channel partial sum / sumsq (deterministic, conflict-free LDS)
    if (tid < 128) {
        float s = 0.f, q = 0.f;
        #pragma unroll 4
        for (int r2 = 0; r2 < 256; ++r2) {
            float v = ep[r2 * 132 + tid];
            s += v;
            q = fmaf(v, v, q);
        }
        g_psum[(size_t)bid * 128 + tid] = s;
        g_psq [(size_t)bid * 128 + tid] = q;
    }

    // coalesced stores of the raw tile
    {
        float4* out4 = (float4*)out;
        const size_t rbase = (size_t)k * NPTS + (size_t)m_base;
        for (int i = tid; i < 8192; i += 512) {
            int row = i >> 5, c4 = i & 31;
            float4 v = *(float4*)&ep[row * 132 + c4 * 4];
            out4[(rbase + (size_t)row) * 32 + c4] = v;
        }
    }
}

// ---------------- stats reduce: 2048 partials -> scale/shift ----------------
__global__ void __launch_bounds__(1024)
reduce_kernel(const float* __restrict__ gamma,
              const float* __restrict__ beta) {
    __shared__ float ss[1024];
    __shared__ float sq[1024];
    const int ch = blockIdx.x;
    const int tid = threadIdx.x;
    float s = 0.f, q = 0.f;
    for (int j = tid; j < 2048; j += 1024) {
        s += g_psum[(size_t)j * 128 + ch];
        q += g_psq [(size_t)j * 128 + ch];
    }
    ss[tid] = s; sq[tid] = q;
    __syncthreads();
    for (int off = 512; off > 0; off >>= 1) {
        if (tid < off) { ss[tid] += ss[tid + off]; sq[tid] += sq[tid + off]; }
        __syncthreads();
    }
    if (tid == 0) {
        float mean = ss[0] / NTOT;
        float var  = sq[0] / NTOT - mean * mean;
        float sc   = gamma[ch] * rsqrtf(var + 1e-5f);
        g_scale[ch] = sc;
        g_shift[ch] = beta[ch] - mean * sc;
    }
}

// ---------------- fused affine + ReLU, in place, float4 ----------------
__global__ void norm_kernel(float* __restrict__ out) {
    const size_t n4 = (size_t)NPTS * KOFF * 32;  // rows * (128/4)
    float4* o = (float4*)out;
    for (size_t i = (size_t)blockIdx.x * blockDim.x + threadIdx.x; i < n4;
         i += (size_t)gridDim.x * blockDim.x) {
        int g = (int)(i & 31);
        float4 sc = ((const float4*)g_scale)[g];
        float4 sh = ((const float4*)g_shift)[g];
        float4 v = o[i];
        v.x = fmaxf(fmaf(v.x, sc.x, sh.x), 0.f);
        v.y = fmaxf(fmaf(v.y, sc.y, sh.y), 0.f);
        v.z = fmaxf(fmaf(v.z, sc.z, sh.z), 0.f);
        v.w = fmaxf(fmaf(v.w, sc.w, sh.w), 0.f);
        o[i] = v;
    }
}

// ---------------- launch ----------------
extern "C" void kernel_launch(void* const* d_in, const int* in_sizes, int n_in,
                              void* d_out, int out_size) {
    const float* x     = (const float*)d_in[0];
    const float* W     = (const float*)d_in[1];
    const float* gamma = (const float*)d_in[2];
    const float* beta  = (const float*)d_in[3];
    float* out = (float*)d_out;

    cudaFuncSetAttribute(gemm_bn_kernel,
                         cudaFuncAttributeMaxDynamicSharedMemorySize, SM_DYN);

    prep_x_kernel<<<2048, 256>>>(x);
    prep_w_kernel<<<1024, 256>>>(W);
    gemm_bn_kernel<<<dim3(8, 256), 512, SM_DYN>>>(out);
    reduce_kernel<<<128, 1024>>>(gamma, beta);
    norm_kernel<<<16384, 256>>>(out);
}